// round 2
// baseline (speedup 1.0000x reference)
#include <cuda_runtime.h>
#include <cuda_bf16.h>
#include <cstdint>

// GroupConv2d: x[16,1024,56,56] f32, w[1024,2,3,3] f32, groups=512, VALID -> out[16,1024,54,54] f32
// One CTA per (batch, group). Group input (2ch x 56x56 = 25KB) staged in SMEM via one
// coalesced float4 sweep; each thread produces a 4-wide strip for both out-channels.

constexpr int HIN = 56, WIN = 56;
constexpr int HOUT = 54, WOUT = 54;
constexpr int IPG = 2, OPG = 2, KS = 3;
constexpr int GROUPS = 512;
constexpr int NBATCH = 16;
constexpr int TPB = 256;
constexpr int IN_PLANE = HIN * WIN;              // 3136
constexpr int IN_ELEMS = IPG * IN_PLANE;         // 6272
constexpr int NCHUNK = 14;                        // ceil(54/4)
constexpr int NW = OPG * IPG * KS * KS;           // 36 weights per group

__global__ __launch_bounds__(TPB) void gconv_kernel(
    const float* __restrict__ x,
    const float* __restrict__ w,
    float* __restrict__ out)
{
    const int bid = blockIdx.x;
    const int g = bid % GROUPS;
    const int n = bid / GROUPS;

    // +8 pad: edge chunk (ow0=52) reads 2 floats past the last row harmlessly.
    __shared__ float s_in[IN_ELEMS + 8];
    __shared__ float s_w[NW];

    // ---- stage input: 6272 contiguous floats = 1568 float4, fully coalesced ----
    const float4* src = reinterpret_cast<const float4*>(
        x + ((size_t)n * (GROUPS * IPG) + (size_t)g * IPG) * IN_PLANE);
    float4* dst = reinterpret_cast<float4*>(s_in);
    #pragma unroll
    for (int i = threadIdx.x; i < IN_ELEMS / 4; i += TPB)
        dst[i] = src[i];

    if (threadIdx.x < NW)
        s_w[threadIdx.x] = w[(size_t)g * NW + threadIdx.x];
    __syncthreads();

    // ---- weights to registers (broadcast LDS, conflict-free) ----
    float wr[NW];
    #pragma unroll
    for (int i = 0; i < NW; i++) wr[i] = s_w[i];

    float* outp = out + ((size_t)n * (GROUPS * OPG) + (size_t)g * OPG) * (HOUT * WOUT);

    // work item = (out row r, 4-wide chunk c); 54 * 14 = 756 items
    for (int item = threadIdx.x; item < HOUT * NCHUNK; item += TPB) {
        const int r = item / NCHUNK;
        const int c = item - r * NCHUNK;
        const int ow0 = c * 4;

        float acc[OPG][4];
        #pragma unroll
        for (int o = 0; o < OPG; o++)
            #pragma unroll
            for (int j = 0; j < 4; j++) acc[o][j] = 0.0f;

        #pragma unroll
        for (int ic = 0; ic < IPG; ic++) {
            #pragma unroll
            for (int kh = 0; kh < KS; kh++) {
                const float* row = &s_in[ic * IN_PLANE + (r + kh) * WIN + ow0];
                // ow0 % 4 == 0 and row stride 56 -> 16B-aligned LDS.128 + 8B LDS.64
                const float4 v0 = *reinterpret_cast<const float4*>(row);
                const float2 v1 = *reinterpret_cast<const float2*>(row + 4);
                const float in6[6] = {v0.x, v0.y, v0.z, v0.w, v1.x, v1.y};
                #pragma unroll
                for (int o = 0; o < OPG; o++) {
                    const float* wk = &wr[o * (IPG * KS * KS) + ic * (KS * KS) + kh * KS];
                    #pragma unroll
                    for (int j = 0; j < 4; j++) {
                        acc[o][j] = fmaf(wk[0], in6[j],
                                    fmaf(wk[1], in6[j + 1],
                                    fmaf(wk[2], in6[j + 2], acc[o][j])));
                    }
                }
            }
        }

        // row offset r*54 floats = 216B*r -> 8B aligned; ow0 multiple of 4 -> float2 stores ok
        #pragma unroll
        for (int o = 0; o < OPG; o++) {
            float* op = outp + o * (HOUT * WOUT) + r * WOUT + ow0;
            if (ow0 + 4 <= WOUT) {
                reinterpret_cast<float2*>(op)[0] = make_float2(acc[o][0], acc[o][1]);
                reinterpret_cast<float2*>(op)[1] = make_float2(acc[o][2], acc[o][3]);
            } else {
                // last chunk: only 2 valid outputs (52, 53)
                reinterpret_cast<float2*>(op)[0] = make_float2(acc[o][0], acc[o][1]);
            }
        }
    }
}

extern "C" void kernel_launch(void* const* d_in, const int* in_sizes, int n_in,
                              void* d_out, int out_size)
{
    const float* x = (const float*)d_in[0];
    const float* w = (const float*)d_in[1];
    float* out = (float*)d_out;

    gconv_kernel<<<NBATCH * GROUPS, TPB>>>(x, w, out);
}